// round 9
// baseline (speedup 1.0000x reference)
#include <cuda_runtime.h>
#include <math.h>

#define BB   128
#define TT   128
#define IDIM 512
#define HDIM 512
#define DD   1024
#define NC   513
#define TB   128
#define MBIG (TB*BB)
#define NBLK 128
#define NTHR 256
#define WPAD 640
#define EPSL 1e-5f

// ---------------- device scratch (no runtime allocation) ----------------------
__device__ float g_X0[MBIG*DD];
__device__ float g_X1[MBIG*DD];
__device__ float g_P [MBIG*NC];
__device__ float g_Wp[1024*WPAD];
__device__ float g_Ust[1024*512];
__device__ float g_Uc0[1024];
__device__ float g_R[16*BB*512];
__device__ float g_H[BB*DD];
__device__ float g_fk[BB], g_hv[BB];
__device__ float g_fkseq[2][TB*BB], g_hvseq[2][TB*BB];
__device__ unsigned g_barcnt;
__device__ unsigned g_barrel;

// ---------------- software grid barrier (all 128 blocks resident) -------------
// Monotonic-counter barrier with generation release. Spin uses __nanosleep
// backoff so 127 waiting blocks don't storm the release line with atomics.
__device__ __forceinline__ void gsync(unsigned &gen) {
    __syncthreads();
    if (threadIdx.x == 0) {
        gen++;
        __threadfence();
        unsigned arrived = atomicAdd(&g_barcnt, 1u) + 1u;
        if (arrived == gen * (unsigned)NBLK) {
            atomicExch(&g_barrel, gen);
        } else {
            while (atomicAdd(&g_barrel, 0u) < gen) { __nanosleep(64); }
        }
        __threadfence();
    }
    __syncthreads();
}

// ---------------- prep: repack W/U, reset barrier, build X0 -------------------
__global__ void prep_pack(const float* __restrict__ W, const float* __restrict__ U) {
    int idx = blockIdx.x * blockDim.x + threadIdx.x;
    if (idx == 0) { g_barcnt = 0u; g_barrel = 0u; }
    const int N1 = 1024*WPAD, N2 = 1024*512;
    if (idx < N1) {
        int k = idx / WPAD, c = idx % WPAD;
        g_Wp[idx] = (c < NC) ? W[k*NC + c] : 0.f;
    } else if (idx < N1 + N2) {
        int l = idx - N1; int k = l >> 9, j = l & 511;
        g_Ust[l] = U[k*NC + 1 + j];
    } else if (idx < N1 + N2 + 1024) {
        int k = idx - N1 - N2;
        g_Uc0[k] = U[k*NC];
    }
}

__global__ void prep_x(const float* __restrict__ x) {
    int idx = blockIdx.x * blockDim.x + threadIdx.x;
    if (idx >= MBIG*DD) return;
    int r = idx >> 10, d = idx & 1023;
    int t = r >> 7, b = r & 127;
    g_X0[idx] = (d < IDIM) ? x[(b*TT + t)*IDIM + d] : 0.f;
}

// ---------------- the persistent kernel ---------------------------------------
extern "C" __global__ void __launch_bounds__(NTHR, 1)
persist_kernel(const int* __restrict__ mask, const float* __restrict__ bvec,
               const float* __restrict__ gam, const float* __restrict__ bet,
               float* __restrict__ out)
{
    extern __shared__ float sm[];
    const int g = blockIdx.x;
    const int tid = threadIdx.x;
    unsigned gen = 0;

    for (int v = 0; v < 4; v++) {
        const float* __restrict__ Xc = (v & 1) ? g_X1 : g_X0;
        float* __restrict__ Xn = (v & 1) ? g_X0 : g_X1;
        const int kLen = v ? DD : IDIM;   // layer 0: padded half of X is zero
        const int wsel = v & 1, rsel = wsel ^ 1;

        // ===== phase: big GEMM  P = Xc @ Wp  (raw; LN0 folded into gate) ======
        {
            float* sA = sm;          // [8][128]
            float* sB = sm + 1024;   // [8][128]
            const int ty = tid >> 4, tx = tid & 15;
            for (int tile = g; tile < 128*5; tile += NBLK) {
                int m0 = (tile / 5) << 7;
                int n0 = (tile % 5) << 7;
                float acc[8][8];
#pragma unroll
                for (int i = 0; i < 8; i++)
#pragma unroll
                    for (int j = 0; j < 8; j++) acc[i][j] = 0.f;

                for (int kt = 0; kt < kLen; kt += 8) {
                    {
                        int m = tid >> 1, kq = tid & 1;
                        float4 va = *(const float4*)(Xc + (size_t)(m0 + m)*DD + kt + kq*4);
                        sA[(kq*4+0)*128 + m] = va.x;
                        sA[(kq*4+1)*128 + m] = va.y;
                        sA[(kq*4+2)*128 + m] = va.z;
                        sA[(kq*4+3)*128 + m] = va.w;
                    }
                    {
                        int kr = tid >> 5, c4 = tid & 31;
                        *(float4*)(sB + kr*128 + c4*4) =
                            *(const float4*)(g_Wp + (size_t)(kt + kr)*WPAD + n0 + c4*4);
                    }
                    __syncthreads();
#pragma unroll
                    for (int k = 0; k < 8; k++) {
                        float a[8], bq[8];
                        *(float4*)(a)    = *(const float4*)(sA + k*128 + ty*8);
                        *(float4*)(a+4)  = *(const float4*)(sA + k*128 + ty*8 + 4);
                        *(float4*)(bq)   = *(const float4*)(sB + k*128 + tx*8);
                        *(float4*)(bq+4) = *(const float4*)(sB + k*128 + tx*8 + 4);
#pragma unroll
                        for (int i = 0; i < 8; i++)
#pragma unroll
                            for (int j = 0; j < 8; j++) acc[i][j] += a[i]*bq[j];
                    }
                    __syncthreads();
                }
#pragma unroll
                for (int i = 0; i < 8; i++) {
                    size_t row = (size_t)(m0 + ty*8 + i);
#pragma unroll
                    for (int j = 0; j < 8; j++) {
                        int c = n0 + tx*8 + j;
                        if (c < NC) g_P[row*NC + c] = acc[i][j];
                    }
                }
            }
        }
        gsync(gen);

        // ===== time loop ======================================================
        for (int t = 0; t < TB; t++) {
            if (t > 0) {
                // recurrent GEMM R = H @ Ust, k-split: block g -> (p = g>>3, ntile = g&7)
                const int p  = g >> 3;
                const int n0 = (g & 7) << 6;
                const int k0 = p << 6;
                float* sA = sm;          // [64][128]
                float* sB = sm + 8192;   // [64][64]
#pragma unroll
                for (int j = 0; j < 8; j++) {
                    int f4 = tid + j*256;
                    int m = f4 & 127, kq = f4 >> 7;
                    float4 va = *(const float4*)(g_H + m*DD + k0 + kq*4);
                    sA[(kq*4+0)*128 + m] = va.x;
                    sA[(kq*4+1)*128 + m] = va.y;
                    sA[(kq*4+2)*128 + m] = va.z;
                    sA[(kq*4+3)*128 + m] = va.w;
                }
#pragma unroll
                for (int j = 0; j < 4; j++) {
                    int f4 = tid + j*256;
                    int kr = f4 >> 4, c4 = f4 & 15;
                    *(float4*)(sB + kr*64 + c4*4) =
                        *(const float4*)(g_Ust + (size_t)(k0 + kr)*512 + n0 + c4*4);
                }
                __syncthreads();
                const int ty = tid >> 3, tx = tid & 7;
                float acc[4][8];
#pragma unroll
                for (int i = 0; i < 4; i++)
#pragma unroll
                    for (int j = 0; j < 8; j++) acc[i][j] = 0.f;
#pragma unroll 8
                for (int k = 0; k < 64; k++) {
                    float a[4], bq[8];
                    *(float4*)(a)    = *(const float4*)(sA + k*128 + ty*4);
                    *(float4*)(bq)   = *(const float4*)(sB + k*64 + tx*8);
                    *(float4*)(bq+4) = *(const float4*)(sB + k*64 + tx*8 + 4);
#pragma unroll
                    for (int i = 0; i < 4; i++)
#pragma unroll
                        for (int j = 0; j < 8; j++) acc[i][j] += a[i]*bq[j];
                }
#pragma unroll
                for (int i = 0; i < 4; i++) {
                    int m = ty*4 + i;
                    float* dst = g_R + (((p*BB + m) << 9) + n0 + tx*8);
                    *(float4*)(dst)   = make_float4(acc[i][0], acc[i][1], acc[i][2], acc[i][3]);
                    *(float4*)(dst+4) = make_float4(acc[i][4], acc[i][5], acc[i][6], acc[i][7]);
                }
            }
            gsync(gen);

            // ---- gate for batch row b = g -----------------------------------
            {
                const int b = g;
                float* sR = sm;              // [513] LN1 input (R0 at [0])
                float* sP = sm + 516;        // [513] raw P row
                float* rd = sm + 1032;       // 5 x 256 reduction
                float* sc = sm + 1032 + 1280;// [8] broadcast scalars
                const size_t r = (size_t)t*BB + b;

                float r0p = 0.f, s1 = 0.f, s2 = 0.f, sp1 = 0.f, sp2 = 0.f;
                if (t > 0) {
                    for (int k = tid; k < DD; k += NTHR)
                        r0p += g_H[b*DD + k] * g_Uc0[k];
                    for (int j = tid; j < 512; j += NTHR) {
                        float vsum = 0.f;
#pragma unroll
                        for (int p = 0; p < 16; p++) vsum += g_R[((p*BB + b) << 9) + j];
                        sR[j+1] = vsum; s1 += vsum; s2 += vsum*vsum;
                    }
                } else {
                    for (int j = tid; j < 512; j += NTHR) sR[j+1] = 0.f;
                }
                for (int c = tid; c < NC; c += NTHR) {
                    float pv = g_P[r*NC + c];
                    sP[c] = pv; sp1 += pv; sp2 += pv*pv;
                }
                rd[tid] = r0p; rd[256+tid] = s1; rd[512+tid] = s2;
                rd[768+tid] = sp1; rd[1024+tid] = sp2;
                __syncthreads();
                for (int s = 128; s > 0; s >>= 1) {
                    if (tid < s) {
                        rd[tid]      += rd[tid+s];
                        rd[256+tid]  += rd[256+tid+s];
                        rd[512+tid]  += rd[512+tid+s];
                        rd[768+tid]  += rd[768+tid+s];
                        rd[1024+tid] += rd[1024+tid+s];
                    }
                    __syncthreads();
                }
                if (tid == 0) {
                    float R0 = rd[0];
                    sR[0] = R0;
                    float sum1 = rd[256] + R0;
                    float ssq1 = rd[512] + R0*R0;
                    float mean1 = sum1 / (float)NC;
                    float var1  = ssq1 / (float)NC - mean1*mean1;
                    if (var1 < 0.f) var1 = 0.f;
                    float inv1 = 1.f / (sqrtf(var1 + EPSL) + EPSL);
                    float mean0 = rd[768] / (float)NC;
                    float var0  = rd[1024] / (float)NC - mean0*mean0;
                    if (var0 < 0.f) var0 = 0.f;
                    float inv0 = 1.f / (sqrtf(var0 + EPSL) + EPSL);

                    float sum2_0 = gam[NC]*((R0 - mean1)*inv1) + bet[NC];
                    float s_0    = gam[0]*((sP[0] - mean0)*inv0) + bet[0] + sum2_0 + bvec[0];
                    float fk_both = fminf(fmaxf(0.2f*s_0 + 0.5f, 0.f), 1.f);
                    float fk_t1   = fminf(fmaxf(0.2f*(sum2_0 + bvec[0]) + 0.5f, 0.f), 1.f);

                    float fk_tm1  = (t > 0) ? g_fk[b] : 0.f;
                    float hv_tm1  = (t > 0) ? g_hv[b] : 0.f;
                    float fkp_tm1 = v ? g_fkseq[rsel][t*BB + b] : 0.f;
                    float fkp     = (v && t < TB-1) ? g_fkseq[rsel][(t+1)*BB + b] : 0.f;
                    float hvp     = v ? g_hvseq[rsel][t*BB + b] : 1.f;

                    int mk  = mask[b*TT + t] > 0;
                    int mk2 = (t > 0) && (mask[b*TT + t - 1] > 0) && !mk;

                    float fk = fkp_tm1 + (1.f - fkp_tm1)*(fk_tm1*fk_both + (1.f - fk_tm1)*fk_t1);
                    if (mk2) fk = 0.f;
                    float ho = hv_tm1 * fk * (fkp + (1.f - fkp)*(1.f - hvp));
                    float xo = hvp * (1.f - fkp) * (1.f - fk + fk*(1.f - hv_tm1));
                    float bo = (1.f - fkp) * fk * hv_tm1 * hvp;
                    float hv = 1.f - (1.f - ho)*(1.f - xo)*(1.f - bo);

                    float fk_out = mk ? fk : fk_tm1; if (mk2) fk_out = 0.f;
                    float hv_out = mk ? hv : hv_tm1;
                    g_fk[b] = fk_out; g_hv[b] = hv_out;
                    g_fkseq[wsel][t*BB + b] = fk_out;
                    g_hvseq[wsel][t*BB + b] = hv_out;

                    sc[0] = mean1; sc[1] = inv1; sc[2] = mean0; sc[3] = inv0;
                    sc[4] = ho; sc[5] = xo; sc[6] = bo; sc[7] = mk ? 1.f : 0.f;
                }
                __syncthreads();
                float mean1 = sc[0], inv1 = sc[1], mean0 = sc[2], inv0 = sc[3];
                float ho = sc[4], xo = sc[5], bo = sc[6];
                bool mk = sc[7] > 0.5f;

                for (int d = tid; d < DD; d += NTHR) {
                    float h_tm1 = (t > 0) ? g_H[b*DD + d] : 0.f;
                    float hval;
                    if (mk) {
                        float xv = Xc[r*DD + d];
                        float hnew = 0.f;
                        if (d >= IDIM) {
                            int c = d - IDIM + 1;   // 1..512
                            float s2c = gam[NC + c]*((sR[c] - mean1)*inv1) + bet[NC + c];
                            float s0c = gam[c]*((sP[c] - mean0)*inv0) + bet[c];
                            hnew = tanhf(s0c + s2c + bvec[c]);
                        }
                        hval = ho*h_tm1 + xo*xv + bo*hnew;
                    } else {
                        hval = h_tm1;
                    }
                    g_H[b*DD + d] = hval;
                    Xn[r*DD + d]  = hval;
                    if (v == 3 && t == TB-1 && d >= IDIM)
                        out[b*HDIM + (d - IDIM)] = hval;
                }
            }
            gsync(gen);
        }
    }
}

// ---------------- host driver: 3 graph nodes, launches only -------------------
extern "C" void kernel_launch(void* const* d_in, const int* in_sizes, int n_in,
                              void* d_out, int out_size) {
    (void)in_sizes; (void)n_in; (void)out_size;
    const float* x    = (const float*)d_in[0];
    const int*   mask = (const int*)  d_in[1];
    const float* W    = (const float*)d_in[2];
    const float* U    = (const float*)d_in[3];
    const float* bvec = (const float*)d_in[4];
    const float* gam  = (const float*)d_in[5];
    const float* bet  = (const float*)d_in[6];
    float* out = (float*)d_out;

    {
        int ntot = 1024*WPAD + 1024*512 + 1024;
        prep_pack<<<(ntot + 255)/256, 256>>>(W, U);
        prep_x<<<(MBIG*DD + 255)/256, 256>>>(x);
    }
    // 49152 B dynamic smem == default limit; no attribute call needed.
    persist_kernel<<<NBLK, NTHR, 49152>>>(mask, bvec, gam, bet, out);
}

// round 10
// speedup vs baseline: 2.1337x; 2.1337x over previous
#include <cuda_runtime.h>
#include <math.h>

#define BB   128
#define TT   128
#define IDIM 512
#define HDIM 512
#define DD   1024
#define NC   513
#define TB   128
#define MBIG (TB*BB)
#define NBLK 128
#define NTHR 512
#define EPSL 1e-5f

typedef unsigned long long u64;

// ---------------- device scratch (no runtime allocation) ----------------------
__device__ float g_X0[MBIG*DD];
__device__ float g_X1[MBIG*DD];
__device__ float g_P [MBIG*512];     // cols 0..511 of LN-input X@W (raw)
__device__ float g_P512[MBIG];       // col 512
__device__ float g_Wp[1024*512];     // W cols 0..511
__device__ float g_w512[1024];       // W col 512
__device__ float g_Ust[1024*512];    // U cols 1..512
__device__ float g_Uc0[1024];        // U col 0
__device__ float g_R[16*BB*512];     // k-split partials of H @ Ust
__device__ float g_H[BB*DD];
__device__ float g_fk[BB], g_hv[BB];
__device__ float g_fkseq[2][TB*BB], g_hvseq[2][TB*BB];
__device__ unsigned g_barcnt;
__device__ unsigned g_barrel;

// ---------------- f32x2 packed-FMA helpers (bit-exact fp32 per lane) ----------
__device__ __forceinline__ u64 pk2(float v) {
    u64 r; asm("mov.b64 %0, {%1, %2};" : "=l"(r) : "f"(v), "f"(v)); return r;
}
__device__ __forceinline__ void fma2(u64 &d, u64 a, u64 b) {
    asm("fma.rn.f32x2 %0, %1, %2, %0;" : "+l"(d) : "l"(a), "l"(b));
}
__device__ __forceinline__ float2 upk(u64 v) {
    float2 r; asm("mov.b64 {%0, %1}, %2;" : "=f"(r.x), "=f"(r.y) : "l"(v)); return r;
}

// ---------------- software grid barrier (128 co-resident blocks) --------------
__device__ __forceinline__ void gsync(unsigned &gen) {
    __syncthreads();
    if (threadIdx.x == 0) {
        gen++;
        __threadfence();
        unsigned arrived = atomicAdd(&g_barcnt, 1u) + 1u;
        if (arrived == gen * (unsigned)NBLK) {
            atomicExch(&g_barrel, gen);
        } else {
            volatile unsigned* rel = &g_barrel;
            while (*rel < gen) { }
        }
        __threadfence();
    }
    __syncthreads();
}

// ---------------- prep ---------------------------------------------------------
__global__ void prep_pack(const float* __restrict__ W, const float* __restrict__ U) {
    int idx = blockIdx.x * blockDim.x + threadIdx.x;
    if (idx == 0) { g_barcnt = 0u; g_barrel = 0u; }
    const int N1 = 1024*512, N2 = 1024*512;
    if (idx < N1) {
        int k = idx >> 9, c = idx & 511;
        g_Wp[idx] = W[k*NC + c];
    } else if (idx < N1 + N2) {
        int l = idx - N1; int k = l >> 9, j = l & 511;
        g_Ust[l] = U[k*NC + 1 + j];
    } else if (idx < N1 + N2 + 1024) {
        int k = idx - N1 - N2;
        g_w512[k] = W[k*NC + 512];
    } else if (idx < N1 + N2 + 2048) {
        int k = idx - N1 - N2 - 1024;
        g_Uc0[k] = U[k*NC];
    }
}

__global__ void prep_x(const float* __restrict__ x) {
    int idx = blockIdx.x * blockDim.x + threadIdx.x;
    if (idx >= MBIG*DD) return;
    int r = idx >> 10, d = idx & 1023;
    int t = r >> 7, b = r & 127;
    g_X0[idx] = (d < IDIM) ? x[(b*TT + t)*IDIM + d] : 0.f;
}

// ---------------- persistent kernel --------------------------------------------
extern "C" __global__ void __launch_bounds__(NTHR, 1)
persist_kernel(const int* __restrict__ mask, const float* __restrict__ bvec,
               const float* __restrict__ gam, const float* __restrict__ bet,
               float* __restrict__ out)
{
    extern __shared__ float sm[];
    const int g = blockIdx.x;
    const int tid = threadIdx.x;
    unsigned gen = 0;

    for (int v = 0; v < 4; v++) {
        const float* __restrict__ Xc = (v & 1) ? g_X1 : g_X0;
        float* __restrict__ Xn = (v & 1) ? g_X0 : g_X1;
        const int kLen = v ? DD : IDIM;
        const int wsel = v & 1, rsel = wsel ^ 1;

        // ===== big GEMM: P = Xc @ Wp (128x256 tiles, BK=8, double-buffered) ===
        {
            float* sA = sm;            // [2][8][128]
            float* sB = sm + 2048;     // [2][8][256] (split j4/tx layout)
            const int ty = tid >> 5;   // 0..15 -> rows ty*8
            const int tx = tid & 31;   // 0..31 -> cols tx*8
            const int m0 = g << 7;
            const int lm = tid >> 2;         // A-load row 0..127
            const int lk = (tid & 3) * 2;    // A-load k 0,2,4,6
            const int bkr = tid >> 6;        // B-load k 0..7
            const int bc0 = (tid & 63) * 4;  // B-load col 0..252
            const int bdst = ((bc0 >> 2) & 1) * 128 + (bc0 >> 3) * 4;
            const int kSteps = kLen >> 3;

            for (int tile = 0; tile < 2; tile++) {
                const int n0 = tile << 8;
                u64 acc2[4][8];
#pragma unroll
                for (int i2 = 0; i2 < 4; i2++)
#pragma unroll
                    for (int j = 0; j < 8; j++) acc2[i2][j] = 0ull;

                float2 pa = *(const float2*)(Xc + (size_t)(m0 + lm)*DD + lk);
                float4 pb = *(const float4*)(g_Wp + (size_t)bkr*512 + n0 + bc0);
                sA[lk*128 + lm] = pa.x; sA[(lk+1)*128 + lm] = pa.y;
                *(float4*)(sB + bkr*256 + bdst) = pb;
                __syncthreads();

                for (int s = 0; s < kSteps; s++) {
                    const int cur = s & 1, nxt = cur ^ 1;
                    if (s + 1 < kSteps) {
                        int kt = (s + 1) << 3;
                        pa = *(const float2*)(Xc + (size_t)(m0 + lm)*DD + kt + lk);
                        pb = *(const float4*)(g_Wp + (size_t)(kt + bkr)*512 + n0 + bc0);
                    }
                    const float* cA = sA + cur*1024;
                    const float* cB = sB + cur*2048;
#pragma unroll
                    for (int k = 0; k < 8; k++) {
                        ulonglong2 av0 = *(const ulonglong2*)(cA + k*128 + ty*8);
                        ulonglong2 av1 = *(const ulonglong2*)(cA + k*128 + ty*8 + 4);
                        float4 b0 = *(const float4*)(cB + k*256 + tx*4);
                        float4 b1 = *(const float4*)(cB + k*256 + 128 + tx*4);
                        u64 a0 = av0.x, a1 = av0.y, a2r = av1.x, a3 = av1.y;
                        float bb[8] = {b0.x,b0.y,b0.z,b0.w, b1.x,b1.y,b1.z,b1.w};
#pragma unroll
                        for (int j = 0; j < 8; j++) {
                            u64 b2 = pk2(bb[j]);
                            fma2(acc2[0][j], a0, b2);
                            fma2(acc2[1][j], a1, b2);
                            fma2(acc2[2][j], a2r, b2);
                            fma2(acc2[3][j], a3, b2);
                        }
                    }
                    if (s + 1 < kSteps) {
                        float* nA = sA + nxt*1024;
                        float* nB = sB + nxt*2048;
                        nA[lk*128 + lm] = pa.x; nA[(lk+1)*128 + lm] = pa.y;
                        *(float4*)(nB + bkr*256 + bdst) = pb;
                    }
                    __syncthreads();
                }
                // writeback: rows m0+ty*8+2*i2(+1), cols n0+tx*8..+7
#pragma unroll
                for (int i2 = 0; i2 < 4; i2++) {
                    float2 f[8];
#pragma unroll
                    for (int j = 0; j < 8; j++) f[j] = upk(acc2[i2][j]);
                    size_t rowA = (size_t)(m0 + ty*8 + i2*2);
                    float* dA = g_P + rowA*512 + n0 + tx*8;
                    float* dB = g_P + (rowA + 1)*512 + n0 + tx*8;
                    *(float4*)(dA)     = make_float4(f[0].x, f[1].x, f[2].x, f[3].x);
                    *(float4*)(dA + 4) = make_float4(f[4].x, f[5].x, f[6].x, f[7].x);
                    *(float4*)(dB)     = make_float4(f[0].y, f[1].y, f[2].y, f[3].y);
                    *(float4*)(dB + 4) = make_float4(f[4].y, f[5].y, f[6].y, f[7].y);
                }
            }
            // column 512: one warp per row
            {
                const int w = tid >> 5, lane = tid & 31;
                for (int rr = w; rr < 128; rr += 16) {
                    const float* xr = Xc + (size_t)(m0 + rr)*DD;
                    float s = 0.f;
                    for (int k = lane; k < kLen; k += 32) s += xr[k] * g_w512[k];
#pragma unroll
                    for (int o = 16; o; o >>= 1) s += __shfl_xor_sync(0xffffffffu, s, o);
                    if (lane == 0) g_P512[m0 + rr] = s;
                }
            }
        }
        gsync(gen);

        // ===== time loop ======================================================
        for (int t = 0; t < TB; t++) {
            if (t > 0) {
                // recurrent GEMM: block g -> (k-chunk p=g>>3, n-tile g&7)
                const int p  = g >> 3;
                const int n0 = (g & 7) << 6;
                const int k0 = p << 6;
                float* sA = sm;           // [64][128]
                float* sB = sm + 8192;    // [64][64] split layout
#pragma unroll
                for (int j = 0; j < 4; j++) {        // A: 2048 float4
                    int f4 = tid + j*512;
                    int m = f4 & 127;
                    int kq = (f4 >> 7) * 4;
                    float4 va = *(const float4*)(g_H + m*DD + k0 + kq);
                    sA[(kq+0)*128 + m] = va.x;
                    sA[(kq+1)*128 + m] = va.y;
                    sA[(kq+2)*128 + m] = va.z;
                    sA[(kq+3)*128 + m] = va.w;
                }
#pragma unroll
                for (int j = 0; j < 2; j++) {        // B: 1024 float4
                    int f4 = tid + j*512;
                    int kr = f4 >> 4;
                    int cc0 = (f4 & 15) * 4;
                    int dst = ((cc0 >> 2) & 1) * 32 + (cc0 >> 3) * 4;
                    *(float4*)(sB + kr*64 + dst) =
                        *(const float4*)(g_Ust + (size_t)(k0 + kr)*512 + n0 + cc0);
                }
                __syncthreads();
                if (tid < 128) {
                    const int ty = tid >> 3, tx = tid & 7;
                    u64 acc2[4][8];
#pragma unroll
                    for (int i2 = 0; i2 < 4; i2++)
#pragma unroll
                        for (int j = 0; j < 8; j++) acc2[i2][j] = 0ull;
#pragma unroll 8
                    for (int k = 0; k < 64; k++) {
                        ulonglong2 av0 = *(const ulonglong2*)(sA + k*128 + ty*8);
                        ulonglong2 av1 = *(const ulonglong2*)(sA + k*128 + ty*8 + 4);
                        float4 b0 = *(const float4*)(sB + k*64 + tx*4);
                        float4 b1 = *(const float4*)(sB + k*64 + 32 + tx*4);
                        u64 a0 = av0.x, a1 = av0.y, a2r = av1.x, a3 = av1.y;
                        float bb[8] = {b0.x,b0.y,b0.z,b0.w, b1.x,b1.y,b1.z,b1.w};
#pragma unroll
                        for (int j = 0; j < 8; j++) {
                            u64 b2 = pk2(bb[j]);
                            fma2(acc2[0][j], a0, b2);
                            fma2(acc2[1][j], a1, b2);
                            fma2(acc2[2][j], a2r, b2);
                            fma2(acc2[3][j], a3, b2);
                        }
                    }
#pragma unroll
                    for (int i2 = 0; i2 < 4; i2++) {
                        float2 f[8];
#pragma unroll
                        for (int j = 0; j < 8; j++) f[j] = upk(acc2[i2][j]);
                        int rowA = ty*8 + i2*2;
                        float* dA = g_R + ((p*BB + rowA) << 9) + n0 + tx*8;
                        float* dB = g_R + ((p*BB + rowA + 1) << 9) + n0 + tx*8;
                        *(float4*)(dA)     = make_float4(f[0].x, f[1].x, f[2].x, f[3].x);
                        *(float4*)(dA + 4) = make_float4(f[4].x, f[5].x, f[6].x, f[7].x);
                        *(float4*)(dB)     = make_float4(f[0].y, f[1].y, f[2].y, f[3].y);
                        *(float4*)(dB + 4) = make_float4(f[4].y, f[5].y, f[6].y, f[7].y);
                    }
                }
            }
            gsync(gen);

            // ---- gate for batch row b = g -----------------------------------
            {
                const int b = g;
                float* sR = sm;               // [513] (R0 at [0])
                float* sP = sm + 516;         // [513]
                float* rd = sm + 1032;        // 5 x 512
                float* sc = sm + 1032 + 2560; // [8]
                const size_t r = (size_t)t*BB + b;

                float r0p = 0.f, s1 = 0.f, s2 = 0.f, sp1 = 0.f, sp2 = 0.f;
                if (t > 0) {
                    for (int k = tid; k < DD; k += NTHR)
                        r0p += g_H[b*DD + k] * g_Uc0[k];
                    for (int j = tid; j < 512; j += NTHR) {
                        float vsum = 0.f;
#pragma unroll
                        for (int p = 0; p < 16; p++) vsum += g_R[((p*BB + b) << 9) + j];
                        sR[j+1] = vsum; s1 += vsum; s2 += vsum*vsum;
                    }
                } else {
                    for (int j = tid; j < 512; j += NTHR) sR[j+1] = 0.f;
                }
                for (int c = tid; c < NC; c += NTHR) {
                    float pv = (c < 512) ? g_P[r*512 + c] : g_P512[r];
                    sP[c] = pv; sp1 += pv; sp2 += pv*pv;
                }
                rd[tid] = r0p; rd[512+tid] = s1; rd[1024+tid] = s2;
                rd[1536+tid] = sp1; rd[2048+tid] = sp2;
                __syncthreads();
                for (int s = 256; s > 0; s >>= 1) {
                    if (tid < s) {
                        rd[tid]      += rd[tid+s];
                        rd[512+tid]  += rd[512+tid+s];
                        rd[1024+tid] += rd[1024+tid+s];
                        rd[1536+tid] += rd[1536+tid+s];
                        rd[2048+tid] += rd[2048+tid+s];
                    }
                    __syncthreads();
                }
                if (tid == 0) {
                    float R0 = rd[0];
                    sR[0] = R0;
                    float sum1 = rd[512] + R0;
                    float ssq1 = rd[1024] + R0*R0;
                    float mean1 = sum1 / (float)NC;
                    float var1  = ssq1 / (float)NC - mean1*mean1;
                    if (var1 < 0.f) var1 = 0.f;
                    float inv1 = 1.f / (sqrtf(var1 + EPSL) + EPSL);
                    float mean0 = rd[1536] / (float)NC;
                    float var0  = rd[2048] / (float)NC - mean0*mean0;
                    if (var0 < 0.f) var0 = 0.f;
                    float inv0 = 1.f / (sqrtf(var0 + EPSL) + EPSL);

                    float sum2_0 = gam[NC]*((R0 - mean1)*inv1) + bet[NC];
                    float s_0    = gam[0]*((sP[0] - mean0)*inv0) + bet[0] + sum2_0 + bvec[0];
                    float fk_both = fminf(fmaxf(0.2f*s_0 + 0.5f, 0.f), 1.f);
                    float fk_t1   = fminf(fmaxf(0.2f*(sum2_0 + bvec[0]) + 0.5f, 0.f), 1.f);

                    float fk_tm1  = (t > 0) ? g_fk[b] : 0.f;
                    float hv_tm1  = (t > 0) ? g_hv[b] : 0.f;
                    float fkp_tm1 = v ? g_fkseq[rsel][t*BB + b] : 0.f;
                    float fkp     = (v && t < TB-1) ? g_fkseq[rsel][(t+1)*BB + b] : 0.f;
                    float hvp     = v ? g_hvseq[rsel][t*BB + b] : 1.f;

                    int mk  = mask[b*TT + t] > 0;
                    int mk2 = (t > 0) && (mask[b*TT + t - 1] > 0) && !mk;

                    float fk = fkp_tm1 + (1.f - fkp_tm1)*(fk_tm1*fk_both + (1.f - fk_tm1)*fk_t1);
                    if (mk2) fk = 0.f;
                    float ho = hv_tm1 * fk * (fkp + (1.f - fkp)*(1.f - hvp));
                    float xo = hvp * (1.f - fkp) * (1.f - fk + fk*(1.f - hv_tm1));
                    float bo = (1.f - fkp) * fk * hv_tm1 * hvp;
                    float hv = 1.f - (1.f - ho)*(1.f - xo)*(1.f - bo);

                    float fk_out = mk ? fk : fk_tm1; if (mk2) fk_out = 0.f;
                    float hv_out = mk ? hv : hv_tm1;
                    g_fk[b] = fk_out; g_hv[b] = hv_out;
                    g_fkseq[wsel][t*BB + b] = fk_out;
                    g_hvseq[wsel][t*BB + b] = hv_out;

                    sc[0] = mean1; sc[1] = inv1; sc[2] = mean0; sc[3] = inv0;
                    sc[4] = ho; sc[5] = xo; sc[6] = bo; sc[7] = mk ? 1.f : 0.f;
                }
                __syncthreads();
                float mean1 = sc[0], inv1 = sc[1], mean0 = sc[2], inv0 = sc[3];
                float ho = sc[4], xo = sc[5], bo = sc[6];
                bool mk = sc[7] > 0.5f;

                for (int d = tid; d < DD; d += NTHR) {
                    float h_tm1 = (t > 0) ? g_H[b*DD + d] : 0.f;
                    float hval;
                    if (mk) {
                        float xv = Xc[r*DD + d];
                        float hnew = 0.f;
                        if (d >= IDIM) {
                            int c = d - IDIM + 1;   // 1..512
                            float s2c = gam[NC + c]*((sR[c] - mean1)*inv1) + bet[NC + c];
                            float s0c = gam[c]*((sP[c] - mean0)*inv0) + bet[c];
                            hnew = tanhf(s0c + s2c + bvec[c]);
                        }
                        hval = ho*h_tm1 + xo*xv + bo*hnew;
                    } else {
                        hval = h_tm1;
                    }
                    g_H[b*DD + d] = hval;
                    Xn[r*DD + d]  = hval;
                    if (v == 3 && t == TB-1 && d >= IDIM)
                        out[b*HDIM + (d - IDIM)] = hval;
                }
            }
            gsync(gen);
        }
    }
}

// ---------------- host driver: 3 graph nodes ----------------------------------
extern "C" void kernel_launch(void* const* d_in, const int* in_sizes, int n_in,
                              void* d_out, int out_size) {
    (void)in_sizes; (void)n_in; (void)out_size;
    const float* x    = (const float*)d_in[0];
    const int*   mask = (const int*)  d_in[1];
    const float* W    = (const float*)d_in[2];
    const float* U    = (const float*)d_in[3];
    const float* bvec = (const float*)d_in[4];
    const float* gam  = (const float*)d_in[5];
    const float* bet  = (const float*)d_in[6];
    float* out = (float*)d_out;

    {
        int ntot = 1024*512 + 1024*512 + 2048;
        prep_pack<<<(ntot + 255)/256, 256>>>(W, U);
        prep_x<<<(MBIG*DD + 255)/256, 256>>>(x);
    }
    persist_kernel<<<NBLK, NTHR, 49152>>>(mask, bvec, gam, bet, out);
}

// round 14
// speedup vs baseline: 2.1706x; 1.0173x over previous
#include <cuda_runtime.h>
#include <math.h>

#define BB   128
#define TT   128
#define IDIM 512
#define HDIM 512
#define DD   1024
#define NC   513
#define TB   128
#define MBIG (TB*BB)
#define NBLK 128
#define NTHR 512
#define EPSL 1e-5f

typedef unsigned long long u64;

// ---------------- device scratch (no runtime allocation) ----------------------
__device__ float g_X0[MBIG*DD];
__device__ float g_X1[MBIG*DD];
__device__ float g_P [MBIG*512];     // cols 0..511 of raw X@W
__device__ float g_P512[MBIG];       // col 512
__device__ float g_Wp[1024*512];     // W cols 0..511
__device__ float g_w512[1024];       // W col 512
__device__ float g_Ust[1024*512];    // U cols 1..512 (k-major)
__device__ float g_Uc0[1024];        // U col 0
__device__ float g_R[16*BB*512];     // k-split partials of H @ Ust
__device__ float g_H[BB*DD];
__device__ float g_fk[BB], g_hv[BB];
__device__ float g_fkseq[2][TB*BB], g_hvseq[2][TB*BB];
__device__ unsigned g_barcnt;
__device__ unsigned g_barrel;

// ---------------- f32x2 packed-FMA helpers (bit-exact fp32 per lane) ----------
__device__ __forceinline__ u64 pk2(float v) {
    u64 r; asm("mov.b64 %0, {%1, %2};" : "=l"(r) : "f"(v), "f"(v)); return r;
}
__device__ __forceinline__ void fma2(u64 &d, u64 a, u64 b) {
    asm("fma.rn.f32x2 %0, %1, %2, %0;" : "+l"(d) : "l"(a), "l"(b));
}
__device__ __forceinline__ float2 upk(u64 v) {
    float2 r; asm("mov.b64 {%0, %1}, %2;" : "=f"(r.x), "=f"(r.y) : "l"(v)); return r;
}

// ---------------- software grid barrier (128 co-resident blocks) --------------
__device__ __forceinline__ void gsync(unsigned &gen) {
    __syncthreads();
    if (threadIdx.x == 0) {
        gen++;
        __threadfence();
        unsigned arrived = atomicAdd(&g_barcnt, 1u) + 1u;
        if (arrived == gen * (unsigned)NBLK) {
            atomicExch(&g_barrel, gen);
        } else {
            volatile unsigned* rel = &g_barrel;
            while (*rel < gen) { }
        }
        __threadfence();
    }
    __syncthreads();
}

// ---------------- single prep kernel (2 launches/call total) ------------------
__global__ void prep_all(const float* __restrict__ x, const float* __restrict__ W,
                         const float* __restrict__ U) {
    int idx = blockIdx.x * blockDim.x + threadIdx.x;
    if (idx == 0) { g_barcnt = 0u; g_barrel = 0u; }
    if (idx < MBIG*DD) {
        int r = idx >> 10, d = idx & 1023;
        int t = r >> 7, b = r & 127;
        g_X0[idx] = (d < IDIM) ? x[(b*TT + t)*IDIM + d] : 0.f;
        return;
    }
    int j = idx - MBIG*DD;
    const int N1 = 1024*512;
    if (j < N1) {
        int k = j >> 9, c = j & 511;
        g_Wp[j] = W[k*NC + c];
    } else if (j < 2*N1) {
        int l = j - N1; int k = l >> 9, c = l & 511;
        g_Ust[l] = U[k*NC + 1 + c];
    } else if (j < 2*N1 + 1024) {
        int k = j - 2*N1;
        g_w512[k] = W[k*NC + 512];
    } else if (j < 2*N1 + 2048) {
        int k = j - 2*N1 - 1024;
        g_Uc0[k] = U[k*NC];
    }
}

// ---------------- persistent kernel --------------------------------------------
extern "C" __global__ void __launch_bounds__(NTHR, 1)
persist_kernel(const int* __restrict__ mask, const float* __restrict__ bvec,
               const float* __restrict__ gam, const float* __restrict__ bet,
               float* __restrict__ out)
{
    extern __shared__ float sm[];
    const int g = blockIdx.x;
    const int tid = threadIdx.x;
    const int wid = tid >> 5, lane = tid & 31;
    unsigned gen = 0;

    for (int v = 0; v < 4; v++) {
        const float* __restrict__ Xc = (v & 1) ? g_X1 : g_X0;
        float* __restrict__ Xn = (v & 1) ? g_X0 : g_X1;
        const int kLen = v ? DD : IDIM;
        const int wsel = v & 1, rsel = wsel ^ 1;

        // ===== big GEMM: P = Xc @ Wp; 128x128 tiles, 8x4 threads, BK=8 ========
        {
            float* sA = sm;            // [2][8][128]
            float* sB = sm + 2048;     // [2][8][128]
            const int ty = tid >> 5;   // 0..15: rows ty*8..+7
            const int tx = tid & 31;   // 0..31: cols tx*4..+3
            const int m0 = g << 7;
            const int lm = tid >> 2, lk = (tid & 3) * 2;   // A loader
            const int bkr = tid >> 6, bc = (tid & 63) * 2; // B loader
            const int kSteps = kLen >> 3;

            for (int nt = 0; nt < 4; nt++) {
                const int n0 = nt << 7;
                u64 acc2[4][4];
#pragma unroll
                for (int i2 = 0; i2 < 4; i2++)
#pragma unroll
                    for (int j = 0; j < 4; j++) acc2[i2][j] = 0ull;

                float2 pa = *(const float2*)(Xc + (size_t)(m0 + lm)*DD + lk);
                float2 pb = *(const float2*)(g_Wp + (size_t)bkr*512 + n0 + bc);
                sA[lk*128 + lm] = pa.x; sA[(lk+1)*128 + lm] = pa.y;
                sB[bkr*128 + bc] = pb.x; sB[bkr*128 + bc + 1] = pb.y;
                __syncthreads();

                for (int s = 0; s < kSteps; s++) {
                    const int cur = s & 1, nxt = cur ^ 1;
                    if (s + 1 < kSteps) {
                        int kt = (s + 1) << 3;
                        pa = *(const float2*)(Xc + (size_t)(m0 + lm)*DD + kt + lk);
                        pb = *(const float2*)(g_Wp + (size_t)(kt + bkr)*512 + n0 + bc);
                    }
                    const float* cA = sA + cur*1024;
                    const float* cB = sB + cur*1024;
#pragma unroll
                    for (int k = 0; k < 8; k++) {
                        ulonglong2 av0 = *(const ulonglong2*)(cA + k*128 + ty*8);
                        ulonglong2 av1 = *(const ulonglong2*)(cA + k*128 + ty*8 + 4);
                        float4 b4 = *(const float4*)(cB + k*128 + tx*4);
                        u64 b0 = pk2(b4.x), b1 = pk2(b4.y), b2 = pk2(b4.z), b3 = pk2(b4.w);
                        fma2(acc2[0][0], av0.x, b0); fma2(acc2[0][1], av0.x, b1);
                        fma2(acc2[0][2], av0.x, b2); fma2(acc2[0][3], av0.x, b3);
                        fma2(acc2[1][0], av0.y, b0); fma2(acc2[1][1], av0.y, b1);
                        fma2(acc2[1][2], av0.y, b2); fma2(acc2[1][3], av0.y, b3);
                        fma2(acc2[2][0], av1.x, b0); fma2(acc2[2][1], av1.x, b1);
                        fma2(acc2[2][2], av1.x, b2); fma2(acc2[2][3], av1.x, b3);
                        fma2(acc2[3][0], av1.y, b0); fma2(acc2[3][1], av1.y, b1);
                        fma2(acc2[3][2], av1.y, b2); fma2(acc2[3][3], av1.y, b3);
                    }
                    if (s + 1 < kSteps) {
                        float* nA = sA + nxt*1024;
                        float* nB = sB + nxt*1024;
                        nA[lk*128 + lm] = pa.x; nA[(lk+1)*128 + lm] = pa.y;
                        nB[bkr*128 + bc] = pb.x; nB[bkr*128 + bc + 1] = pb.y;
                    }
                    __syncthreads();
                }
#pragma unroll
                for (int i2 = 0; i2 < 4; i2++) {
                    float2 f0 = upk(acc2[i2][0]), f1 = upk(acc2[i2][1]);
                    float2 f2 = upk(acc2[i2][2]), f3 = upk(acc2[i2][3]);
                    size_t rowA = (size_t)(m0 + ty*8 + i2*2);
                    *(float4*)(g_P + rowA*512 + n0 + tx*4)     = make_float4(f0.x, f1.x, f2.x, f3.x);
                    *(float4*)(g_P + (rowA+1)*512 + n0 + tx*4) = make_float4(f0.y, f1.y, f2.y, f3.y);
                }
            }
            // column 512: one warp per row
            for (int rr = wid; rr < 128; rr += 16) {
                const float* xr = Xc + (size_t)(m0 + rr)*DD;
                float s = 0.f;
                for (int k = lane; k < kLen; k += 32) s += xr[k] * g_w512[k];
#pragma unroll
                for (int o = 16; o; o >>= 1) s += __shfl_xor_sync(0xffffffffu, s, o);
                if (lane == 0) g_P512[m0 + rr] = s;
            }
        }
        gsync(gen);

        // ===== time loop ======================================================
        for (int t = 0; t < TB; t++) {
            if (t > 0) {
                // rec GEMM: block g -> (k-chunk p = g>>3, n-tile g&7); all 512 thr
                const int p  = g >> 3;
                const int n0 = (g & 7) << 6;
                const int k0 = p << 6;
                float* sA = sm;           // [64][128]
                float* sB = sm + 8192;    // [64][64]
#pragma unroll
                for (int j = 0; j < 4; j++) {
                    int f4 = tid + j*512;
                    int m = f4 & 127;
                    int kq = (f4 >> 7) * 4;
                    float4 va = *(const float4*)(g_H + m*DD + k0 + kq);
                    sA[(kq+0)*128 + m] = va.x;
                    sA[(kq+1)*128 + m] = va.y;
                    sA[(kq+2)*128 + m] = va.z;
                    sA[(kq+3)*128 + m] = va.w;
                }
#pragma unroll
                for (int j = 0; j < 2; j++) {
                    int f4 = tid + j*512;
                    int kr = f4 >> 4;
                    int cc0 = (f4 & 15) * 4;
                    *(float4*)(sB + kr*64 + cc0) =
                        *(const float4*)(g_Ust + (size_t)(k0 + kr)*512 + n0 + cc0);
                }
                __syncthreads();
                const int ty = tid >> 4;   // 0..31: rows ty*4..+3
                const int tx = tid & 15;   // 0..15: cols tx*4..+3
                u64 acc2[2][4];
#pragma unroll
                for (int i2 = 0; i2 < 2; i2++)
#pragma unroll
                    for (int j = 0; j < 4; j++) acc2[i2][j] = 0ull;
#pragma unroll 8
                for (int k = 0; k < 64; k++) {
                    ulonglong2 av = *(const ulonglong2*)(sA + k*128 + ty*4);
                    float4 b4 = *(const float4*)(sB + k*64 + tx*4);
                    u64 b0 = pk2(b4.x), b1 = pk2(b4.y), b2 = pk2(b4.z), b3 = pk2(b4.w);
                    fma2(acc2[0][0], av.x, b0); fma2(acc2[0][1], av.x, b1);
                    fma2(acc2[0][2], av.x, b2); fma2(acc2[0][3], av.x, b3);
                    fma2(acc2[1][0], av.y, b0); fma2(acc2[1][1], av.y, b1);
                    fma2(acc2[1][2], av.y, b2); fma2(acc2[1][3], av.y, b3);
                }
#pragma unroll
                for (int i2 = 0; i2 < 2; i2++) {
                    float2 f0 = upk(acc2[i2][0]), f1 = upk(acc2[i2][1]);
                    float2 f2 = upk(acc2[i2][2]), f3 = upk(acc2[i2][3]);
                    int rowA = ty*4 + i2*2;
                    *(float4*)(g_R + ((p*BB + rowA) << 9) + n0 + tx*4)     = make_float4(f0.x, f1.x, f2.x, f3.x);
                    *(float4*)(g_R + ((p*BB + rowA + 1) << 9) + n0 + tx*4) = make_float4(f0.y, f1.y, f2.y, f3.y);
                }
            }
            gsync(gen);

            // ---- gate for batch row b = g -----------------------------------
            {
                const int b = g;
                float* sR = sm;               // [513] (R0 at [0], unused by d-loop)
                float* sP = sm + 516;         // [513]
                float* rp = sm + 1032;        // [5][16] warp partials
                float* sc = sm + 1032 + 80;   // [8]
                const size_t r = (size_t)t*BB + b;

                float r0p = 0.f, s1 = 0.f, s2 = 0.f, sp1 = 0.f, sp2 = 0.f;
                if (t > 0) {
                    for (int k = tid; k < DD; k += NTHR)
                        r0p += g_H[b*DD + k] * g_Uc0[k];
                    for (int j = tid; j < 512; j += NTHR) {
                        float vsum = 0.f;
#pragma unroll
                        for (int p = 0; p < 16; p++) vsum += g_R[((p*BB + b) << 9) + j];
                        sR[j+1] = vsum; s1 += vsum; s2 += vsum*vsum;
                    }
                } else {
                    for (int j = tid; j < 512; j += NTHR) sR[j+1] = 0.f;
                }
                for (int c = tid; c < NC; c += NTHR) {
                    float pv = (c < 512) ? g_P[r*512 + c] : g_P512[r];
                    sP[c] = pv; sp1 += pv; sp2 += pv*pv;
                }
#pragma unroll
                for (int o = 16; o; o >>= 1) {
                    r0p += __shfl_xor_sync(0xffffffffu, r0p, o);
                    s1  += __shfl_xor_sync(0xffffffffu, s1,  o);
                    s2  += __shfl_xor_sync(0xffffffffu, s2,  o);
                    sp1 += __shfl_xor_sync(0xffffffffu, sp1, o);
                    sp2 += __shfl_xor_sync(0xffffffffu, sp2, o);
                }
                if (lane == 0) {
                    rp[wid] = r0p; rp[16+wid] = s1; rp[32+wid] = s2;
                    rp[48+wid] = sp1; rp[64+wid] = sp2;
                }
                __syncthreads();
                if (wid == 0) {
                    float v0 = (lane < 16) ? rp[lane]    : 0.f;
                    float v1 = (lane < 16) ? rp[16+lane] : 0.f;
                    float v2 = (lane < 16) ? rp[32+lane] : 0.f;
                    float v3 = (lane < 16) ? rp[48+lane] : 0.f;
                    float v4 = (lane < 16) ? rp[64+lane] : 0.f;
#pragma unroll
                    for (int o = 8; o; o >>= 1) {
                        v0 += __shfl_xor_sync(0xffffffffu, v0, o);
                        v1 += __shfl_xor_sync(0xffffffffu, v1, o);
                        v2 += __shfl_xor_sync(0xffffffffu, v2, o);
                        v3 += __shfl_xor_sync(0xffffffffu, v3, o);
                        v4 += __shfl_xor_sync(0xffffffffu, v4, o);
                    }
                    if (lane == 0) {
                        float R0 = v0;
                        float sum1 = v1 + R0;
                        float ssq1 = v2 + R0*R0;
                        float mean1 = sum1 / (float)NC;
                        float var1  = ssq1 / (float)NC - mean1*mean1;
                        if (var1 < 0.f) var1 = 0.f;
                        float inv1 = 1.f / (sqrtf(var1 + EPSL) + EPSL);
                        float mean0 = v3 / (float)NC;
                        float var0  = v4 / (float)NC - mean0*mean0;
                        if (var0 < 0.f) var0 = 0.f;
                        float inv0 = 1.f / (sqrtf(var0 + EPSL) + EPSL);

                        float sum2_0 = gam[NC]*((R0 - mean1)*inv1) + bet[NC];
                        float s_0    = gam[0]*((sP[0] - mean0)*inv0) + bet[0] + sum2_0 + bvec[0];
                        float fk_both = fminf(fmaxf(0.2f*s_0 + 0.5f, 0.f), 1.f);
                        float fk_t1   = fminf(fmaxf(0.2f*(sum2_0 + bvec[0]) + 0.5f, 0.f), 1.f);

                        float fk_tm1  = (t > 0) ? g_fk[b] : 0.f;
                        float hv_tm1  = (t > 0) ? g_hv[b] : 0.f;
                        float fkp_tm1 = v ? g_fkseq[rsel][t*BB + b] : 0.f;
                        float fkp     = (v && t < TB-1) ? g_fkseq[rsel][(t+1)*BB + b] : 0.f;
                        float hvp     = v ? g_hvseq[rsel][t*BB + b] : 1.f;

                        int mk  = mask[b*TT + t] > 0;
                        int mk2 = (t > 0) && (mask[b*TT + t - 1] > 0) && !mk;

                        float fk = fkp_tm1 + (1.f - fkp_tm1)*(fk_tm1*fk_both + (1.f - fk_tm1)*fk_t1);
                        if (mk2) fk = 0.f;
                        float ho = hv_tm1 * fk * (fkp + (1.f - fkp)*(1.f - hvp));
                        float xo = hvp * (1.f - fkp) * (1.f - fk + fk*(1.f - hv_tm1));
                        float bo = (1.f - fkp) * fk * hv_tm1 * hvp;
                        float hv = 1.f - (1.f - ho)*(1.f - xo)*(1.f - bo);

                        float fk_out = mk ? fk : fk_tm1; if (mk2) fk_out = 0.f;
                        float hv_out = mk ? hv : hv_tm1;
                        g_fk[b] = fk_out; g_hv[b] = hv_out;
                        g_fkseq[wsel][t*BB + b] = fk_out;
                        g_hvseq[wsel][t*BB + b] = hv_out;

                        sc[0] = mean1; sc[1] = inv1; sc[2] = mean0; sc[3] = inv0;
                        sc[4] = ho; sc[5] = xo; sc[6] = bo; sc[7] = mk ? 1.f : 0.f;
                    }
                }
                __syncthreads();
                float mean1 = sc[0], inv1 = sc[1], mean0 = sc[2], inv0 = sc[3];
                float ho = sc[4], xo = sc[5], bo = sc[6];
                bool mk = sc[7] > 0.5f;

                for (int d = tid; d < DD; d += NTHR) {
                    float h_tm1 = (t > 0) ? g_H[b*DD + d] : 0.f;
                    float hval;
                    if (mk) {
                        float xv = Xc[r*DD + d];
                        float hnew = 0.f;
                        if (d >= IDIM) {
                            int c = d - IDIM + 1;   // 1..512
                            float s2c = gam[NC + c]*((sR[c] - mean1)*inv1) + bet[NC + c];
                            float s0c = gam[c]*((sP[c] - mean0)*inv0) + bet[c];
                            hnew = tanhf(s0c + s2c + bvec[c]);
                        }
                        hval = ho*h_tm1 + xo*xv + bo*hnew;
                    } else {
                        hval = h_tm1;
                    }
                    g_H[b*DD + d] = hval;
                    Xn[r*DD + d]  = hval;
                    if (v == 3 && t == TB-1 && d >= IDIM)
                        out[b*HDIM + (d - IDIM)] = hval;
                }
            }
            gsync(gen);
        }
    }
}

// ---------------- host driver: 2 graph nodes ----------------------------------
extern "C" void kernel_launch(void* const* d_in, const int* in_sizes, int n_in,
                              void* d_out, int out_size) {
    (void)in_sizes; (void)n_in; (void)out_size;
    const float* x    = (const float*)d_in[0];
    const int*   mask = (const int*)  d_in[1];
    const float* W    = (const float*)d_in[2];
    const float* U    = (const float*)d_in[3];
    const float* bvec = (const float*)d_in[4];
    const float* gam  = (const float*)d_in[5];
    const float* bet  = (const float*)d_in[6];
    float* out = (float*)d_out;

    int ntot = MBIG*DD + 2*1024*512 + 2048;
    prep_all<<<(ntot + 255)/256, 256>>>(x, W, U);
    persist_kernel<<<NBLK, NTHR, 49152>>>(mask, bvec, gam, bet, out);
}

// round 15
// speedup vs baseline: 2.5655x; 1.1819x over previous
#include <cuda_runtime.h>
#include <math.h>

#define BB   128
#define TT   128
#define IDIM 512
#define HDIM 512
#define DD   1024
#define NC   513
#define TB   128
#define MBIG (TB*BB)
#define NBLK 128
#define NTHR 512
#define EPSL 1e-5f

typedef unsigned long long u64;

// ---------------- device scratch (no runtime allocation) ----------------------
__device__ __align__(16) float g_X[4][MBIG*DD];        // X[v] = input rows to layer v
__device__ __align__(16) float g_Wp[1024*512];         // W cols 0..511 (k-major)
__device__ __align__(16) float g_w512[1024];           // W col 512
__device__ __align__(16) float g_Ust[1024*512];        // U cols 1..512 (k-major)
__device__ __align__(16) float g_Uc0[1024];            // U col 0
__device__ __align__(16) float g_Rp[4][4][BB][512];    // R partials  [v][kchunk][b][n]
__device__ __align__(16) float g_Pp[4][2][4][BB][516]; // P partials  [v][t&1][kchunk][b][c]
__device__ __align__(16) float g_H[4][BB][DD];         // per-layer recurrent state
__device__ float g_fkC[4][BB], g_hvC[4][BB];           // fk/hv carries per layer
__device__ float g_fkq[4][TB][BB], g_hvq[4][TB][BB];   // fk/hv sequences per layer
__device__ unsigned g_barcnt;
__device__ unsigned g_barrel;

// ---------------- f32x2 packed-FMA helpers (bit-exact fp32 per lane) ----------
__device__ __forceinline__ u64 pk2(float v) {
    u64 r; asm("mov.b64 %0, {%1, %2};" : "=l"(r) : "f"(v), "f"(v)); return r;
}
__device__ __forceinline__ void fma2(u64 &d, u64 a, u64 b) {
    asm("fma.rn.f32x2 %0, %1, %2, %0;" : "+l"(d) : "l"(a), "l"(b));
}
__device__ __forceinline__ float2 upk(u64 v) {
    float2 r; asm("mov.b64 {%0, %1}, %2;" : "=f"(r.x), "=f"(r.y) : "l"(v)); return r;
}

// ---------------- software grid barrier (128 co-resident blocks) --------------
__device__ __forceinline__ void gsync(unsigned &gen) {
    __syncthreads();
    if (threadIdx.x == 0) {
        gen++;
        __threadfence();
        unsigned arrived = atomicAdd(&g_barcnt, 1u) + 1u;
        if (arrived == gen * (unsigned)NBLK) {
            atomicExch(&g_barrel, gen);
        } else {
            volatile unsigned* rel = &g_barrel;
            while (*rel < gen) { }
        }
        __threadfence();
    }
    __syncthreads();
}

// ---------------- prep kernel --------------------------------------------------
__global__ void prep_all(const float* __restrict__ x, const float* __restrict__ W,
                         const float* __restrict__ U) {
    int idx = blockIdx.x * blockDim.x + threadIdx.x;
    if (idx == 0) { g_barcnt = 0u; g_barrel = 0u; }
    const int NX = MBIG*DD, N1 = 1024*512;
    if (idx < NX) {
        int r = idx >> 10, d = idx & 1023;
        int t = r >> 7, b = r & 127;
        g_X[0][idx] = (d < IDIM) ? x[(b*TT + t)*IDIM + d] : 0.f;
        return;
    }
    int j = idx - NX;
    if (j < N1) {
        int k = j >> 9, c = j & 511;
        g_Wp[j] = W[k*NC + c];
    } else if (j < 2*N1) {
        int l = j - N1; int k = l >> 9, c = l & 511;
        g_Ust[l] = U[k*NC + 1 + c];
    } else if (j < 2*N1 + 1024) {
        int k = j - 2*N1;
        g_w512[k] = W[k*NC + 512];
    } else if (j < 2*N1 + 2048) {
        int k = j - 2*N1 - 1024;
        g_Uc0[k] = U[k*NC];
    }
}

// ---------------- persistent wavefront kernel ----------------------------------
extern "C" __global__ void __launch_bounds__(NTHR, 1)
persist_kernel(const int* __restrict__ mask, const float* __restrict__ bvec,
               const float* __restrict__ gam, const float* __restrict__ bet,
               float* __restrict__ out)
{
    extern __shared__ float sm[];
    const int g = blockIdx.x;
    const int tid = threadIdx.x;
    const int lane = tid & 31;
    unsigned gen = 0;

    for (int s = -1; s <= 133; s++) {
        // ============ GEMM phase: 8 tasks x 16 sub-blocks ====================
        {
            const int task = g >> 4, sub = g & 15;
            const int tv = task >> 1;
            const bool isP = (task & 1) != 0;
            const int t = isP ? (s + 1 - 2*tv) : (s - 2*tv);
            bool valid = isP ? (t >= 0 && t <= 127) : (t >= 1 && t <= 127);
            const int p = sub >> 2, nq = sub & 3;
            if (isP && tv == 0 && p >= 2) valid = false;
            if (valid) {
                const float* Asrc = isP ? (g_X[tv] + ((size_t)t*128)*DD)
                                        : (&g_H[tv][0][0]);
                const float* Bsrc = isP ? g_Wp : g_Ust;
                float* sA = sm;            // [64][128] = 32KB
                float* sB = sm + 8192;     // [64][64]  = 16KB
                const int ty = tid >> 4, tx = tid & 15;
                u64 acc[2][2][4];
#pragma unroll
                for (int a0 = 0; a0 < 2; a0++)
#pragma unroll
                    for (int a1 = 0; a1 < 2; a1++)
#pragma unroll
                        for (int a2 = 0; a2 < 4; a2++) acc[a0][a1][a2] = 0ull;

                for (int kk = 0; kk < 4; kk++) {
                    const int k0 = p*256 + kk*64;
                    __syncthreads();   // previous compute done before restaging
#pragma unroll
                    for (int j = 0; j < 4; j++) {
                        int f4 = tid + j*512;
                        int m = f4 & 127, kq = (f4 >> 7) * 4;
                        float4 va = *(const float4*)(Asrc + (size_t)m*DD + k0 + kq);
                        sA[(kq+0)*128 + m] = va.x;
                        sA[(kq+1)*128 + m] = va.y;
                        sA[(kq+2)*128 + m] = va.z;
                        sA[(kq+3)*128 + m] = va.w;
                    }
                    for (int nt = 0; nt < 2; nt++) {
                        const int n0 = nq*128 + nt*64;
                        if (nt) __syncthreads();
#pragma unroll
                        for (int j = 0; j < 2; j++) {
                            int f4 = tid + j*512;
                            int kr = f4 >> 4, cc = (f4 & 15) * 4;
                            *(float4*)(sB + kr*64 + cc) =
                                *(const float4*)(Bsrc + (size_t)(k0 + kr)*512 + n0 + cc);
                        }
                        __syncthreads();
#pragma unroll 8
                        for (int k = 0; k < 64; k++) {
                            ulonglong2 av = *(const ulonglong2*)(sA + k*128 + ty*4);
                            float4 b4 = *(const float4*)(sB + k*64 + tx*4);
                            u64 b0 = pk2(b4.x), b1 = pk2(b4.y);
                            u64 b2 = pk2(b4.z), b3 = pk2(b4.w);
                            fma2(acc[nt][0][0], av.x, b0); fma2(acc[nt][0][1], av.x, b1);
                            fma2(acc[nt][0][2], av.x, b2); fma2(acc[nt][0][3], av.x, b3);
                            fma2(acc[nt][1][0], av.y, b0); fma2(acc[nt][1][1], av.y, b1);
                            fma2(acc[nt][1][2], av.y, b2); fma2(acc[nt][1][3], av.y, b3);
                        }
                    }
                }
                // write partials
                float* dst = isP ? &g_Pp[tv][t & 1][p][0][0] : &g_Rp[tv][p][0][0];
                const int cs = isP ? 516 : 512;
#pragma unroll
                for (int nt = 0; nt < 2; nt++) {
                    int col = nq*128 + nt*64 + tx*4;
#pragma unroll
                    for (int i2 = 0; i2 < 2; i2++) {
                        float2 f0 = upk(acc[nt][i2][0]), f1 = upk(acc[nt][i2][1]);
                        float2 f2 = upk(acc[nt][i2][2]), f3 = upk(acc[nt][i2][3]);
                        int row = ty*4 + i2*2;
                        *(float4*)(dst + (size_t)row*cs + col)
                            = make_float4(f0.x, f1.x, f2.x, f3.x);
                        *(float4*)(dst + (size_t)(row+1)*cs + col)
                            = make_float4(f0.y, f1.y, f2.y, f3.y);
                    }
                }
                // P col 512 partial (nq==0 blocks)
                if (isP && nq == 0) {
                    int row = tid >> 2, l4 = tid & 3;
                    const float* xr = Asrc + (size_t)row*DD;
                    float ssum = 0.f;
#pragma unroll 16
                    for (int i = 0; i < 64; i++) {
                        int k = p*256 + l4 + i*4;
                        ssum += xr[k] * g_w512[k];
                    }
                    ssum += __shfl_xor_sync(0xffffffffu, ssum, 1);
                    ssum += __shfl_xor_sync(0xffffffffu, ssum, 2);
                    if (l4 == 0) g_Pp[tv][t & 1][p][row][512] = ssum;
                }
            }
        }
        gsync(gen);

        // ============ gate phase: 4 layer-groups of 128 threads ===============
        {
            const int grp = tid >> 7, gtid = tid & 127, gwarp = gtid >> 5;
            const int v2 = grp;
            const int t = s - 2*v2;
            if (t >= 0 && t <= 127) {
                const int b = g;
                float* gp = sm + grp * 1104;
                float* sP = gp;          // [513]
                float* sR = gp + 520;    // [512]  (col c stored at sR[c-1])
                float* red = gp + 1040;  // [20]
                float* bc  = gp + 1064;  // [8]
                const int barid = 1 + grp;

                // early scalar prefetch (gtid 0 only)
                float fk_tm1 = 0.f, hv_tm1 = 0.f, fkp_tm1 = 0.f, fkp = 0.f, hvp = 1.f;
                int mk = 1, mk2 = 0;
                if (gtid == 0) {
                    mk  = mask[b*TT + t] > 0;
                    mk2 = (t > 0) && (mask[b*TT + t - 1] > 0) && !mk;
                    if (t > 0) { fk_tm1 = g_fkC[v2][b]; hv_tm1 = g_hvC[v2][b]; }
                    if (v2 > 0) {
                        fkp_tm1 = g_fkq[v2-1][t][b];
                        fkp     = (t < TB-1) ? g_fkq[v2-1][t+1][b] : 0.f;
                        hvp     = g_hvq[v2-1][t][b];
                    }
                }

                const float* Hrow = &g_H[v2][b][0];
                const float* Xrow = g_X[v2] + ((size_t)t*128 + b)*DD;
                float h8[8], x8[8];
                float r0p = 0.f, s1 = 0.f, s2 = 0.f, sp1 = 0.f, sp2 = 0.f;
#pragma unroll
                for (int i = 0; i < 8; i++) x8[i] = Xrow[gtid + 128*i];
                if (t > 0) {
#pragma unroll
                    for (int i = 0; i < 8; i++) {
                        h8[i] = Hrow[gtid + 128*i];
                        r0p += h8[i] * g_Uc0[gtid + 128*i];
                    }
                } else {
#pragma unroll
                    for (int i = 0; i < 8; i++) h8[i] = 0.f;
                }
                // R sums (4 k-chunk partials)
                if (t > 0) {
                    const float* r0 = &g_Rp[v2][0][b][0];
                    const float* r1 = &g_Rp[v2][1][b][0];
                    const float* r2 = &g_Rp[v2][2][b][0];
                    const float* r3 = &g_Rp[v2][3][b][0];
                    for (int j = gtid; j < 512; j += 128) {
                        float rv = r0[j] + r1[j] + r2[j] + r3[j];
                        sR[j] = rv; s1 += rv; s2 += rv*rv;
                    }
                } else {
                    for (int j = gtid; j < 512; j += 128) sR[j] = 0.f;
                }
                // P sums (2 partials for layer 0, else 4)
                {
                    const int par = t & 1;
                    const float* p0 = &g_Pp[v2][par][0][b][0];
                    const float* p1 = &g_Pp[v2][par][1][b][0];
                    const float* p2 = &g_Pp[v2][par][2][b][0];
                    const float* p3 = &g_Pp[v2][par][3][b][0];
                    const bool four = (v2 != 0);
                    for (int c = gtid; c < 513; c += 128) {
                        float pv = p0[c] + p1[c];
                        if (four) pv += p2[c] + p3[c];
                        sP[c] = pv; sp1 += pv; sp2 += pv*pv;
                    }
                }
#pragma unroll
                for (int o = 16; o; o >>= 1) {
                    r0p += __shfl_xor_sync(0xffffffffu, r0p, o);
                    s1  += __shfl_xor_sync(0xffffffffu, s1,  o);
                    s2  += __shfl_xor_sync(0xffffffffu, s2,  o);
                    sp1 += __shfl_xor_sync(0xffffffffu, sp1, o);
                    sp2 += __shfl_xor_sync(0xffffffffu, sp2, o);
                }
                if (lane == 0) {
                    red[gwarp] = r0p; red[4+gwarp] = s1; red[8+gwarp] = s2;
                    red[12+gwarp] = sp1; red[16+gwarp] = sp2;
                }
                asm volatile("bar.sync %0, %1;" :: "r"(barid), "r"(128) : "memory");
                if (gtid == 0) {
                    float R0  = red[0]+red[1]+red[2]+red[3];
                    float v1s = red[4]+red[5]+red[6]+red[7];
                    float v2s = red[8]+red[9]+red[10]+red[11];
                    float v3s = red[12]+red[13]+red[14]+red[15];
                    float v4s = red[16]+red[17]+red[18]+red[19];
                    float sum1 = v1s + R0;
                    float ssq1 = v2s + R0*R0;
                    float mean1 = sum1 / (float)NC;
                    float var1  = ssq1 / (float)NC - mean1*mean1;
                    if (var1 < 0.f) var1 = 0.f;
                    float inv1 = 1.f / (sqrtf(var1 + EPSL) + EPSL);
                    float mean0 = v3s / (float)NC;
                    float var0  = v4s / (float)NC - mean0*mean0;
                    if (var0 < 0.f) var0 = 0.f;
                    float inv0 = 1.f / (sqrtf(var0 + EPSL) + EPSL);

                    float sum2_0 = gam[NC]*((R0 - mean1)*inv1) + bet[NC];
                    float s_0    = gam[0]*((sP[0] - mean0)*inv0) + bet[0] + sum2_0 + bvec[0];
                    float fk_both = fminf(fmaxf(0.2f*s_0 + 0.5f, 0.f), 1.f);
                    float fk_t1   = fminf(fmaxf(0.2f*(sum2_0 + bvec[0]) + 0.5f, 0.f), 1.f);

                    float fk = fkp_tm1 + (1.f - fkp_tm1)*(fk_tm1*fk_both + (1.f - fk_tm1)*fk_t1);
                    if (mk2) fk = 0.f;
                    float ho = hv_tm1 * fk * (fkp + (1.f - fkp)*(1.f - hvp));
                    float xo = hvp * (1.f - fkp) * (1.f - fk + fk*(1.f - hv_tm1));
                    float bo = (1.f - fkp) * fk * hv_tm1 * hvp;
                    float hv = 1.f - (1.f - ho)*(1.f - xo)*(1.f - bo);

                    float fk_out = mk ? fk : fk_tm1; if (mk2) fk_out = 0.f;
                    float hv_out = mk ? hv : hv_tm1;
                    g_fkC[v2][b] = fk_out; g_hvC[v2][b] = hv_out;
                    g_fkq[v2][t][b] = fk_out; g_hvq[v2][t][b] = hv_out;

                    bc[0] = mean1; bc[1] = inv1; bc[2] = mean0; bc[3] = inv0;
                    bc[4] = ho; bc[5] = xo; bc[6] = bo; bc[7] = mk ? 1.f : 0.f;
                }
                asm volatile("bar.sync %0, %1;" :: "r"(barid), "r"(128) : "memory");
                float mean1 = bc[0], inv1 = bc[1], mean0 = bc[2], inv0 = bc[3];
                float ho = bc[4], xo = bc[5], bo = bc[6];
                bool mkb = bc[7] > 0.5f;

                float* Hw = &g_H[v2][b][0];
                float* Xw = (v2 < 3) ? (g_X[v2+1] + ((size_t)t*128 + b)*DD) : (float*)0;
#pragma unroll
                for (int i = 0; i < 8; i++) {
                    int d = gtid + 128*i;
                    float h_tm1 = h8[i];
                    float hval;
                    if (mkb) {
                        float hnew = 0.f;
                        if (d >= IDIM) {
                            int c = d - IDIM + 1;   // 1..512
                            float s2c = gam[NC + c]*((sR[c-1] - mean1)*inv1) + bet[NC + c];
                            float s0c = gam[c]*((sP[c] - mean0)*inv0) + bet[c];
                            hnew = tanhf(s0c + s2c + bvec[c]);
                        }
                        hval = ho*h_tm1 + xo*x8[i] + bo*hnew;
                    } else {
                        hval = h_tm1;
                    }
                    Hw[d] = hval;
                    if (v2 < 3) Xw[d] = hval;
                    if (v2 == 3 && t == TB-1 && d >= IDIM)
                        out[b*HDIM + (d - IDIM)] = hval;
                }
            }
        }
        gsync(gen);
    }
}

// ---------------- host driver: 2 graph nodes ----------------------------------
extern "C" void kernel_launch(void* const* d_in, const int* in_sizes, int n_in,
                              void* d_out, int out_size) {
    (void)in_sizes; (void)n_in; (void)out_size;
    const float* x    = (const float*)d_in[0];
    const int*   mask = (const int*)  d_in[1];
    const float* W    = (const float*)d_in[2];
    const float* U    = (const float*)d_in[3];
    const float* bvec = (const float*)d_in[4];
    const float* gam  = (const float*)d_in[5];
    const float* bet  = (const float*)d_in[6];
    float* out = (float*)d_out;

    int ntot = MBIG*DD + 2*1024*512 + 2048;
    prep_all<<<(ntot + 255)/256, 256>>>(x, W, U);
    persist_kernel<<<NBLK, NTHR, 49152>>>(mask, bvec, gam, bet, out);
}

// round 17
// speedup vs baseline: 3.0231x; 1.1784x over previous
#include <cuda_runtime.h>
#include <math.h>

#define BB   128
#define TT   128
#define IDIM 512
#define HDIM 512
#define DD   1024
#define NC   513
#define TB   128
#define MBIG (TB*BB)
#define NBLK 128
#define NTHR 512
#define EPSL 1e-5f

typedef unsigned long long u64;

// ---------------- device scratch (no runtime allocation) ----------------------
__device__ __align__(16) float g_X[4][MBIG*DD];        // X[v] = input rows to layer v
__device__ __align__(16) float g_Wp[1024*512];         // W cols 0..511 (k-major)
__device__ __align__(16) float g_w512[1024];           // W col 512
__device__ __align__(16) float g_Ust[1024*512];        // U cols 1..512 (k-major)
__device__ __align__(16) float g_Uc0[1024];            // U col 0
__device__ __align__(16) float g_Rp[4][8][BB][512];    // R partials  [v][kchunk][b][n]
__device__ __align__(16) float g_Pp[4][2][8][BB][516]; // P partials  [v][t&1][kchunk][b][c]
__device__ __align__(16) float g_H[4][BB][DD];         // per-layer recurrent state
__device__ float g_fkC[4][BB], g_hvC[4][BB];           // fk/hv carries per layer
__device__ float g_fkq[4][TB][BB], g_hvq[4][TB][BB];   // fk/hv sequences per layer
__device__ unsigned g_barcnt;
__device__ unsigned g_barrel;

// ---------------- f32x2 packed-FMA helpers (bit-exact fp32 per lane) ----------
__device__ __forceinline__ u64 pk2(float v) {
    u64 r; asm("mov.b64 %0, {%1, %2};" : "=l"(r) : "f"(v), "f"(v)); return r;
}
__device__ __forceinline__ void fma2(u64 &d, u64 a, u64 b) {
    asm("fma.rn.f32x2 %0, %1, %2, %0;" : "+l"(d) : "l"(a), "l"(b));
}
__device__ __forceinline__ float2 upk(u64 v) {
    float2 r; asm("mov.b64 {%0, %1}, %2;" : "=f"(r.x), "=f"(r.y) : "l"(v)); return r;
}

// ---------------- software grid barrier (128 co-resident blocks) --------------
__device__ __forceinline__ void gsync(unsigned &gen) {
    __syncthreads();
    if (threadIdx.x == 0) {
        gen++;
        __threadfence();
        unsigned arrived = atomicAdd(&g_barcnt, 1u) + 1u;
        if (arrived == gen * (unsigned)NBLK) {
            atomicExch(&g_barrel, gen);
        } else {
            volatile unsigned* rel = &g_barrel;
            while (*rel < gen) { }
        }
        __threadfence();
    }
    __syncthreads();
}

// ---------------- prep kernel --------------------------------------------------
__global__ void prep_all(const float* __restrict__ x, const float* __restrict__ W,
                         const float* __restrict__ U) {
    int idx = blockIdx.x * blockDim.x + threadIdx.x;
    if (idx == 0) { g_barcnt = 0u; g_barrel = 0u; }
    const int NX = MBIG*DD, N1 = 1024*512;
    if (idx < NX) {
        int r = idx >> 10, d = idx & 1023;
        int t = r >> 7, b = r & 127;
        g_X[0][idx] = (d < IDIM) ? x[(b*TT + t)*IDIM + d] : 0.f;
        return;
    }
    int j = idx - NX;
    if (j < N1) {
        int k = j >> 9, c = j & 511;
        g_Wp[j] = W[k*NC + c];
    } else if (j < 2*N1) {
        int l = j - N1; int k = l >> 9, c = l & 511;
        g_Ust[l] = U[k*NC + 1 + c];
    } else if (j < 2*N1 + 1024) {
        int k = j - 2*N1;
        g_w512[k] = W[k*NC + 512];
    } else if (j < 2*N1 + 2048) {
        int k = j - 2*N1 - 1024;
        g_Uc0[k] = U[k*NC];
    }
}

// ---------------- persistent wavefront kernel ----------------------------------
extern "C" __global__ void __launch_bounds__(NTHR, 1)
persist_kernel(const int* __restrict__ mask, const float* __restrict__ bvec,
               const float* __restrict__ gam, const float* __restrict__ bet,
               float* __restrict__ out)
{
    extern __shared__ float sm[];
    const int g = blockIdx.x;
    const int tid = threadIdx.x;
    const int lane = tid & 31;
    unsigned gen = 0;

    for (int s = -1; s <= 133; s++) {
        // ============ GEMM phase: 8 tasks x 16 sub-blocks =====================
        // sub-block = (kc 0..7: K slice of 128, nt 0..1: N slice of 256)
        // 512 threads, 8x8 register tiles, A read via warp-broadcast LDS
        {
            const int task = g >> 4, sub = g & 15;
            const int tv = task >> 1;
            const bool isP = (task & 1) != 0;
            const int t = isP ? (s + 1 - 2*tv) : (s - 2*tv);
            bool valid = isP ? (t >= 0 && t <= 127) : (t >= 1 && t <= 127);
            const int kc = sub >> 1, nt = sub & 1;
            if (isP && tv == 0 && kc >= 4) valid = false;   // layer-0 X pad is zero
            if (valid) {
                const float* Asrc = isP ? (g_X[tv] + ((size_t)t*128)*DD)
                                        : (&g_H[tv][0][0]);
                const float* Bsrc = isP ? g_Wp : g_Ust;
                float* sA = sm;            // [32][128] = 16KB
                float* sB = sm + 4096;     // [32][256] = 32KB
                const int ty = tid >> 5;   // warp id 0..15: rows ty*8..+7 (broadcast)
                const int tx = tid & 31;   // lane: cols tx*8..+7
                const int n0 = nt << 8;
                u64 acc[4][8];
#pragma unroll
                for (int i2 = 0; i2 < 4; i2++)
#pragma unroll
                    for (int j = 0; j < 8; j++) acc[i2][j] = 0ull;

                for (int st = 0; st < 4; st++) {
                    const int k0 = kc*128 + st*32;
                    __syncthreads();   // previous stage compute done
#pragma unroll
                    for (int j = 0; j < 2; j++) {          // A: 1024 float4
                        int f4 = tid + j*512;
                        int m = f4 & 127, kq = (f4 >> 7) * 4;
                        float4 va = *(const float4*)(Asrc + (size_t)m*DD + k0 + kq);
                        sA[(kq+0)*128 + m] = va.x;
                        sA[(kq+1)*128 + m] = va.y;
                        sA[(kq+2)*128 + m] = va.z;
                        sA[(kq+3)*128 + m] = va.w;
                    }
#pragma unroll
                    for (int j = 0; j < 4; j++) {          // B: 2048 float4
                        int f4 = tid + j*512;
                        int kr = f4 >> 6, cc = (f4 & 63) * 4;
                        *(float4*)(sB + kr*256 + cc) =
                            *(const float4*)(Bsrc + (size_t)(k0 + kr)*512 + n0 + cc);
                    }
                    __syncthreads();
#pragma unroll 8
                    for (int k = 0; k < 32; k++) {
                        ulonglong2 av0 = *(const ulonglong2*)(sA + k*128 + ty*8);
                        ulonglong2 av1 = *(const ulonglong2*)(sA + k*128 + ty*8 + 4);
                        float4 b0 = *(const float4*)(sB + k*256 + tx*8);
                        float4 b1 = *(const float4*)(sB + k*256 + tx*8 + 4);
                        u64 q0 = pk2(b0.x), q1 = pk2(b0.y), q2 = pk2(b0.z), q3 = pk2(b0.w);
                        u64 q4 = pk2(b1.x), q5 = pk2(b1.y), q6 = pk2(b1.z), q7 = pk2(b1.w);
                        fma2(acc[0][0], av0.x, q0); fma2(acc[0][1], av0.x, q1);
                        fma2(acc[0][2], av0.x, q2); fma2(acc[0][3], av0.x, q3);
                        fma2(acc[0][4], av0.x, q4); fma2(acc[0][5], av0.x, q5);
                        fma2(acc[0][6], av0.x, q6); fma2(acc[0][7], av0.x, q7);
                        fma2(acc[1][0], av0.y, q0); fma2(acc[1][1], av0.y, q1);
                        fma2(acc[1][2], av0.y, q2); fma2(acc[1][3], av0.y, q3);
                        fma2(acc[1][4], av0.y, q4); fma2(acc[1][5], av0.y, q5);
                        fma2(acc[1][6], av0.y, q6); fma2(acc[1][7], av0.y, q7);
                        fma2(acc[2][0], av1.x, q0); fma2(acc[2][1], av1.x, q1);
                        fma2(acc[2][2], av1.x, q2); fma2(acc[2][3], av1.x, q3);
                        fma2(acc[2][4], av1.x, q4); fma2(acc[2][5], av1.x, q5);
                        fma2(acc[2][6], av1.x, q6); fma2(acc[2][7], av1.x, q7);
                        fma2(acc[3][0], av1.y, q0); fma2(acc[3][1], av1.y, q1);
                        fma2(acc[3][2], av1.y, q2); fma2(acc[3][3], av1.y, q3);
                        fma2(acc[3][4], av1.y, q4); fma2(acc[3][5], av1.y, q5);
                        fma2(acc[3][6], av1.y, q6); fma2(acc[3][7], av1.y, q7);
                    }
                }
                // write partials
                float* dst = isP ? &g_Pp[tv][t & 1][kc][0][0] : &g_Rp[tv][kc][0][0];
                const int cs = isP ? 516 : 512;
                const int col = n0 + tx*8;
#pragma unroll
                for (int i2 = 0; i2 < 4; i2++) {
                    float2 f0 = upk(acc[i2][0]), f1 = upk(acc[i2][1]);
                    float2 f2 = upk(acc[i2][2]), f3 = upk(acc[i2][3]);
                    float2 f4 = upk(acc[i2][4]), f5 = upk(acc[i2][5]);
                    float2 f6 = upk(acc[i2][6]), f7 = upk(acc[i2][7]);
                    int row = ty*8 + i2*2;
                    float* dA = dst + (size_t)row*cs + col;
                    float* dB = dst + (size_t)(row+1)*cs + col;
                    *(float4*)(dA)     = make_float4(f0.x, f1.x, f2.x, f3.x);
                    *(float4*)(dA + 4) = make_float4(f4.x, f5.x, f6.x, f7.x);
                    *(float4*)(dB)     = make_float4(f0.y, f1.y, f2.y, f3.y);
                    *(float4*)(dB + 4) = make_float4(f4.y, f5.y, f6.y, f7.y);
                }
                // P col 512 partial (nt==0 blocks cover all kc)
                if (isP && nt == 0) {
                    int row = tid >> 2, l4 = tid & 3;
                    const float* xr = Asrc + (size_t)row*DD;
                    float ssum = 0.f;
#pragma unroll 8
                    for (int i = 0; i < 32; i++) {
                        int k = kc*128 + l4 + i*4;
                        ssum += xr[k] * g_w512[k];
                    }
                    ssum += __shfl_xor_sync(0xffffffffu, ssum, 1);
                    ssum += __shfl_xor_sync(0xffffffffu, ssum, 2);
                    if (l4 == 0) g_Pp[tv][t & 1][kc][row][512] = ssum;
                }
            }
        }
        gsync(gen);

        // ============ gate phase: 4 layer-groups of 128 threads ===============
        {
            const int grp = tid >> 7, gtid = tid & 127, gwarp = gtid >> 5;
            const int v2 = grp;
            const int t = s - 2*v2;
            if (t >= 0 && t <= 127) {
                const int b = g;
                float* gp = sm + grp * 1104;
                float* sP = gp;          // [513]
                float* sR = gp + 520;    // [512]  (col c stored at sR[c-1])
                float* red = gp + 1040;  // [20]
                float* bc  = gp + 1064;  // [8]
                const int barid = 1 + grp;

                float fk_tm1 = 0.f, hv_tm1 = 0.f, fkp_tm1 = 0.f, fkp = 0.f, hvp = 1.f;
                int mk = 1, mk2 = 0;
                if (gtid == 0) {
                    mk  = mask[b*TT + t] > 0;
                    mk2 = (t > 0) && (mask[b*TT + t - 1] > 0) && !mk;
                    if (t > 0) { fk_tm1 = g_fkC[v2][b]; hv_tm1 = g_hvC[v2][b]; }
                    if (v2 > 0) {
                        fkp_tm1 = g_fkq[v2-1][t][b];
                        fkp     = (t < TB-1) ? g_fkq[v2-1][t+1][b] : 0.f;
                        hvp     = g_hvq[v2-1][t][b];
                    }
                }

                const float* Hrow = &g_H[v2][b][0];
                const float* Xrow = g_X[v2] + ((size_t)t*128 + b)*DD;
                float h8[8], x8[8];
                float r0p = 0.f, s1 = 0.f, s2 = 0.f, sp1 = 0.f, sp2 = 0.f;
#pragma unroll
                for (int i = 0; i < 8; i++) x8[i] = Xrow[gtid + 128*i];
                if (t > 0) {
#pragma unroll
                    for (int i = 0; i < 8; i++) {
                        h8[i] = Hrow[gtid + 128*i];
                        r0p += h8[i] * g_Uc0[gtid + 128*i];
                    }
                } else {
#pragma unroll
                    for (int i = 0; i < 8; i++) h8[i] = 0.f;
                }
                // R sums (8 k-chunk partials)
                if (t > 0) {
                    for (int j = gtid; j < 512; j += 128) {
                        float rv = 0.f;
#pragma unroll
                        for (int q = 0; q < 8; q++) rv += g_Rp[v2][q][b][j];
                        sR[j] = rv; s1 += rv; s2 += rv*rv;
                    }
                } else {
                    for (int j = gtid; j < 512; j += 128) sR[j] = 0.f;
                }
                // P sums (4 partials for layer 0, else 8)
                {
                    const int par = t & 1;
                    const int npar = (v2 == 0) ? 4 : 8;
                    for (int c = gtid; c < 513; c += 128) {
                        float pv = 0.f;
                        for (int q = 0; q < npar; q++) pv += g_Pp[v2][par][q][b][c];
                        sP[c] = pv; sp1 += pv; sp2 += pv*pv;
                    }
                }
#pragma unroll
                for (int o = 16; o; o >>= 1) {
                    r0p += __shfl_xor_sync(0xffffffffu, r0p, o);
                    s1  += __shfl_xor_sync(0xffffffffu, s1,  o);
                    s2  += __shfl_xor_sync(0xffffffffu, s2,  o);
                    sp1 += __shfl_xor_sync(0xffffffffu, sp1, o);
                    sp2 += __shfl_xor_sync(0xffffffffu, sp2, o);
                }
                if (lane == 0) {
                    red[gwarp] = r0p; red[4+gwarp] = s1; red[8+gwarp] = s2;
                    red[12+gwarp] = sp1; red[16+gwarp] = sp2;
                }
                asm volatile("bar.sync %0, %1;" :: "r"(barid), "r"(128) : "memory");
                if (gtid == 0) {
                    float R0  = red[0]+red[1]+red[2]+red[3];
                    float v1s = red[4]+red[5]+red[6]+red[7];
                    float v2s = red[8]+red[9]+red[10]+red[11];
                    float v3s = red[12]+red[13]+red[14]+red[15];
                    float v4s = red[16]+red[17]+red[18]+red[19];
                    float sum1 = v1s + R0;
                    float ssq1 = v2s + R0*R0;
                    float mean1 = sum1 / (float)NC;
                    float var1  = ssq1 / (float)NC - mean1*mean1;
                    if (var1 < 0.f) var1 = 0.f;
                    float inv1 = 1.f / (sqrtf(var1 + EPSL) + EPSL);
                    float mean0 = v3s / (float)NC;
                    float var0  = v4s / (float)NC - mean0*mean0;
                    if (var0 < 0.f) var0 = 0.f;
                    float inv0 = 1.f / (sqrtf(var0 + EPSL) + EPSL);

                    float sum2_0 = gam[NC]*((R0 - mean1)*inv1) + bet[NC];
                    float s_0    = gam[0]*((sP[0] - mean0)*inv0) + bet[0] + sum2_0 + bvec[0];
                    float fk_both = fminf(fmaxf(0.2f*s_0 + 0.5f, 0.f), 1.f);
                    float fk_t1   = fminf(fmaxf(0.2f*(sum2_0 + bvec[0]) + 0.5f, 0.f), 1.f);

                    float fk = fkp_tm1 + (1.f - fkp_tm1)*(fk_tm1*fk_both + (1.f - fk_tm1)*fk_t1);
                    if (mk2) fk = 0.f;
                    float ho = hv_tm1 * fk * (fkp + (1.f - fkp)*(1.f - hvp));
                    float xo = hvp * (1.f - fkp) * (1.f - fk + fk*(1.f - hv_tm1));
                    float bo = (1.f - fkp) * fk * hv_tm1 * hvp;
                    float hv = 1.f - (1.f - ho)*(1.f - xo)*(1.f - bo);

                    float fk_out = mk ? fk : fk_tm1; if (mk2) fk_out = 0.f;
                    float hv_out = mk ? hv : hv_tm1;
                    g_fkC[v2][b] = fk_out; g_hvC[v2][b] = hv_out;
                    g_fkq[v2][t][b] = fk_out; g_hvq[v2][t][b] = hv_out;

                    bc[0] = mean1; bc[1] = inv1; bc[2] = mean0; bc[3] = inv0;
                    bc[4] = ho; bc[5] = xo; bc[6] = bo; bc[7] = mk ? 1.f : 0.f;
                }
                asm volatile("bar.sync %0, %1;" :: "r"(barid), "r"(128) : "memory");
                float mean1 = bc[0], inv1 = bc[1], mean0 = bc[2], inv0 = bc[3];
                float ho = bc[4], xo = bc[5], bo = bc[6];
                bool mkb = bc[7] > 0.5f;

                float* Hw = &g_H[v2][b][0];
                float* Xw = (v2 < 3) ? (g_X[v2+1] + ((size_t)t*128 + b)*DD) : (float*)0;
#pragma unroll
                for (int i = 0; i < 8; i++) {
                    int d = gtid + 128*i;
                    float h_tm1 = h8[i];
                    float hval;
                    if (mkb) {
                        float hnew = 0.f;
                        if (d >= IDIM) {
                            int c = d - IDIM + 1;   // 1..512
                            float s2c = gam[NC + c]*((sR[c-1] - mean1)*inv1) + bet[NC + c];
                            float s0c = gam[c]*((sP[c] - mean0)*inv0) + bet[c];
                            hnew = tanhf(s0c + s2c + bvec[c]);
                        }
                        hval = ho*h_tm1 + xo*x8[i] + bo*hnew;
                    } else {
                        hval = h_tm1;
                    }
                    Hw[d] = hval;
                    if (v2 < 3) Xw[d] = hval;
                    if (v2 == 3 && t == TB-1 && d >= IDIM)
                        out[b*HDIM + (d - IDIM)] = hval;
                }
            }
        }
        gsync(gen);
    }
}

// ---------------- host driver: 2 graph nodes ----------------------------------
extern "C" void kernel_launch(void* const* d_in, const int* in_sizes, int n_in,
                              void* d_out, int out_size) {
    (void)in_sizes; (void)n_in; (void)out_size;
    const float* x    = (const float*)d_in[0];
    const int*   mask = (const int*)  d_in[1];
    const float* W    = (const float*)d_in[2];
    const float* U    = (const float*)d_in[3];
    const float* bvec = (const float*)d_in[4];
    const float* gam  = (const float*)d_in[5];
    const float* bet  = (const float*)d_in[6];
    float* out = (float*)d_out;

    int ntot = MBIG*DD + 2*1024*512 + 2048;
    prep_all<<<(ntot + 255)/256, 256>>>(x, W, U);
    persist_kernel<<<NBLK, NTHR, 49152>>>(mask, bvec, gam, bet, out);
}